// round 13
// baseline (speedup 1.0000x reference)
#include <cuda_runtime.h>
#include <cuda_bf16.h>
#include <cuda_fp16.h>

// Problem constants (fixed by dataset)
#define NN 50000
#define DD 128
#define EE 800000
#define RR 2
#define LL 2
#define GG 64
#define CC 8
#define NTOT (RR * NN)                 // 100000 CSR rows (relation-major)
#define NBLK ((NTOT + 1023) / 1024)    // 98 scan blocks

// Scratch (__device__ globals; never referenced from host code)
__device__ float   g_deg[NTOT];
__device__ float   g_inv[NTOT];
__device__ int     g_rowptr[NTOT + 1];
__device__ int     g_cursor[NTOT];
__device__ int     g_bsum[NBLK];
__device__ int     g_boff[NBLK];
__device__ int2    g_csr[RR * EE];       // (src, norm-as-int)
__device__ float   g_xw[RR * NN * DD];   // fp32 xw (self-loop + exactness)
__device__ __half2 g_xwh[RR * NN * (DD / 2)]; // fp16 mirror for edge gathers
__device__ float   g_out[NN * DD];       // layer-2 output (pooled)
__device__ float   g_h[NN * DD];         // hidden after relu
__device__ float   g_sums[GG * DD];
__device__ float   g_cnt[GG];

__device__ __forceinline__ void red_add_v4(float* addr, float a, float b,
                                           float c, float d) {
    asm volatile("red.global.add.v4.f32 [%0], {%1, %2, %3, %4};"
                 :: "l"(addr), "f"(a), "f"(b), "f"(c), "f"(d) : "memory");
}

// ---------------------------------------------------------------------------
__global__ void k_zero() {
    int t = blockIdx.x * blockDim.x + threadIdx.x;
    if (t < NTOT) g_deg[t] = 0.f;
    if (t < GG * DD) g_sums[t] = 0.f;
    if (t < GG) g_cnt[t] = 0.f;
}

// degree count (dst side), per relation
__global__ void k_deg(const int* __restrict__ edges) {
    int t = blockIdx.x * blockDim.x + threadIdx.x;
    if (t >= RR * EE) return;
    int r = (t >= EE) ? 1 : 0;
    int e = t - r * EE;
    int dst = edges[r * 2 * EE + EE + e];
    atomicAdd(&g_deg[r * NN + dst], 1.f);
}

__global__ void k_inv() {
    int t = blockIdx.x * blockDim.x + threadIdx.x;
    if (t >= NTOT) return;
    g_inv[t] = rsqrtf(g_deg[t] + 1.f);
}

// ---------------------------------------------------------------------------
// multi-block scan, phase 1: per-block warp-shuffle scan (1024 threads/block)
__global__ void k_scan1() {
    __shared__ int wsum[32];
    int i = blockIdx.x * 1024 + threadIdx.x;
    int v = (i < NTOT) ? (int)g_deg[i] : 0;
    int lane = threadIdx.x & 31, w = threadIdx.x >> 5;
    int s = v;
#pragma unroll
    for (int o = 1; o < 32; o <<= 1) {
        int t = __shfl_up_sync(0xffffffffu, s, o);
        if (lane >= o) s += t;
    }
    if (lane == 31) wsum[w] = s;
    __syncthreads();
    if (w == 0) {
        int ws = wsum[lane];
#pragma unroll
        for (int o = 1; o < 32; o <<= 1) {
            int t = __shfl_up_sync(0xffffffffu, ws, o);
            if (lane >= o) ws += t;
        }
        wsum[lane] = ws;
    }
    __syncthreads();
    int excl = s - v + (w > 0 ? wsum[w - 1] : 0);
    if (i < NTOT) g_rowptr[i] = excl;
    if (threadIdx.x == 1023) g_bsum[blockIdx.x] = wsum[31];
}

// phase 2: single block (128 threads) scans the 98 block totals
__global__ void k_scan2() {
    __shared__ int wsum[4];
    int lane = threadIdx.x & 31, w = threadIdx.x >> 5;
    int v = (threadIdx.x < NBLK) ? g_bsum[threadIdx.x] : 0;
    int s = v;
#pragma unroll
    for (int o = 1; o < 32; o <<= 1) {
        int t = __shfl_up_sync(0xffffffffu, s, o);
        if (lane >= o) s += t;
    }
    if (lane == 31) wsum[w] = s;
    __syncthreads();
    int base = 0;
    for (int k = 0; k < w; k++) base += wsum[k];
    if (threadIdx.x < NBLK) g_boff[threadIdx.x] = base + s - v;
    if (threadIdx.x == 0) g_rowptr[NTOT] = RR * EE;   // total statically known
}

// phase 3: add block offsets
__global__ void k_scan3() {
    int i = blockIdx.x * blockDim.x + threadIdx.x;
    if (i >= NTOT) return;
    int val = g_rowptr[i] + g_boff[i >> 10];
    g_rowptr[i] = val;
    g_cursor[i] = val;
}

// scatter edge records into CSR buckets; norm precomputed (layer-invariant)
__global__ void k_fill(const int* __restrict__ edges) {
    int t = blockIdx.x * blockDim.x + threadIdx.x;
    if (t >= RR * EE) return;
    int r = (t >= EE) ? 1 : 0;
    int e = t - r * EE;
    int src = edges[r * 2 * EE + e];
    int dst = edges[r * 2 * EE + EE + e];
    int row = r * NN + dst;
    int pos = atomicAdd(&g_cursor[row], 1);
    float norm = g_inv[r * NN + src] * g_inv[row];
    g_csr[pos] = make_int2(src, __float_as_int(norm));
}

// ---------------------------------------------------------------------------
// GEMM: XW[r] = A (N x 128) @ W[l,r] (128 x 128)
// Writes fp32 result AND an fp16 mirror (for halved gather traffic).
__global__ void __launch_bounds__(256, 3)
k_gemm(const float* __restrict__ x_in, int use_h, const float* __restrict__ Wl) {
    const float* __restrict__ A = use_h ? g_h : x_in;
    const int r = blockIdx.y;
    const float* __restrict__ Wr = Wl + r * DD * DD;
    float* __restrict__ out = g_xw + (size_t)r * NN * DD;
    __half2* __restrict__ outh = g_xwh + (size_t)r * NN * (DD / 2);
    const int row0 = blockIdx.x * 64;
    __shared__ float sA[64 * DD];
    const int tid = threadIdx.x;

#pragma unroll
    for (int i = 0; i < 32; i++) {
        int idx = tid + i * 256;
        int rr = idx >> 7, cc = idx & 127;
        int row = row0 + rr;
        sA[idx] = (row < NN) ? A[row * DD + cc] : 0.f;
    }
    __syncthreads();

    const int lane = tid & 31;
    const int w = tid >> 5;
    float4 acc[8];
#pragma unroll
    for (int i = 0; i < 8; i++) acc[i] = make_float4(0.f, 0.f, 0.f, 0.f);

    const float* __restrict__ wp = Wr + lane * 4;
#pragma unroll 8
    for (int k = 0; k < DD; k++) {
        float4 wv = *(const float4*)(wp + k * DD);
#pragma unroll
        for (int rr = 0; rr < 8; rr++) {
            float a = sA[(w * 8 + rr) * DD + k];
            acc[rr].x = fmaf(a, wv.x, acc[rr].x);
            acc[rr].y = fmaf(a, wv.y, acc[rr].y);
            acc[rr].z = fmaf(a, wv.z, acc[rr].z);
            acc[rr].w = fmaf(a, wv.w, acc[rr].w);
        }
    }
#pragma unroll
    for (int rr = 0; rr < 8; rr++) {
        int row = row0 + w * 8 + rr;
        if (row < NN) {
            *(float4*)&out[(size_t)row * DD + lane * 4] = acc[rr];
            union { __half2 h[2]; uint2 u; } pk;
            pk.h[0] = __floats2half2_rn(acc[rr].x, acc[rr].y);
            pk.h[1] = __floats2half2_rn(acc[rr].z, acc[rr].w);
            *(uint2*)&outh[(size_t)row * (DD / 2) + lane * 2] = pk.u;
        }
    }
}

// ---------------------------------------------------------------------------
// CSR gather: warp per node, lane owns 4 cols. Self-loop + biases in fp32;
// edge messages read the fp16 mirror (half the L2 traffic), accumulate fp32.
__global__ void k_gather(const float* __restrict__ bvec, int store_relu) {
    int gw = (blockIdx.x * blockDim.x + threadIdx.x) >> 5;
    if (gw >= NN) return;
    const int lane = threadIdx.x & 31;
    const int n = gw;
    const int c = lane * 4;

    float4 b0 = *(const float4*)&bvec[c];
    float4 b1 = *(const float4*)&bvec[DD + c];
    float i0 = g_inv[n];
    float i1 = g_inv[NN + n];
    float4 x0 = *(const float4*)&g_xw[(size_t)n * DD + c];
    float4 x1 = *(const float4*)&g_xw[(size_t)(NN + n) * DD + c];

    float4 acc;
    acc.x = b0.x + b1.x + x0.x * i0 * i0 + x1.x * i1 * i1;
    acc.y = b0.y + b1.y + x0.y * i0 * i0 + x1.y * i1 * i1;
    acc.z = b0.z + b1.z + x0.z * i0 * i0 + x1.z * i1 * i1;
    acc.w = b0.w + b1.w + x0.w * i0 * i0 + x1.w * i1 * i1;

#pragma unroll
    for (int r = 0; r < RR; r++) {
        const __half2* __restrict__ xwh = g_xwh + (size_t)r * NN * (DD / 2);
        int row = r * NN + n;
        int s0 = g_rowptr[row];
        int s1 = g_rowptr[row + 1];
#pragma unroll 2
        for (int j = s0; j < s1; j++) {
            int2 ed = __ldg(&g_csr[j]);
            float norm = __int_as_float(ed.y);
            union { uint2 u; __half2 h[2]; } pk;
            pk.u = __ldg((const uint2*)&xwh[(size_t)ed.x * (DD / 2) + lane * 2]);
            float2 lo = __half22float2(pk.h[0]);
            float2 hi = __half22float2(pk.h[1]);
            acc.x = fmaf(lo.x, norm, acc.x);
            acc.y = fmaf(lo.y, norm, acc.y);
            acc.z = fmaf(hi.x, norm, acc.z);
            acc.w = fmaf(hi.y, norm, acc.w);
        }
    }

    float* dst = store_relu ? g_h : g_out;
    if (store_relu) {
        acc.x = fmaxf(acc.x, 0.f); acc.y = fmaxf(acc.y, 0.f);
        acc.z = fmaxf(acc.z, 0.f); acc.w = fmaxf(acc.w, 0.f);
    }
    *(float4*)&dst[(size_t)n * DD + c] = acc;
}

// ---------------------------------------------------------------------------
// global mean pool: v4 reductions, 4 floats per thread
__global__ void k_pool(const int* __restrict__ batch) {
    int t = blockIdx.x * blockDim.x + threadIdx.x;
    if (t >= NN * (DD / 4)) return;
    int n = t >> 5;
    int c4 = (t & 31) * 4;
    int g = batch[n];
    float4 v = *(const float4*)&g_out[(size_t)n * DD + c4];
    red_add_v4(&g_sums[g * DD + c4], v.x, v.y, v.z, v.w);
    if (c4 == 0) atomicAdd(&g_cnt[g], 1.f);
}

__global__ void k_final(const float* __restrict__ lw, const float* __restrict__ lb,
                        float* __restrict__ out) {
    int t = threadIdx.x;          // 512 = G*C
    int g = t >> 3, c = t & 7;
    float inv = 1.f / fmaxf(g_cnt[g], 1.f);
    float acc = lb[c];
#pragma unroll 8
    for (int d = 0; d < DD; d++)
        acc = fmaf(g_sums[g * DD + d] * inv, lw[d * CC + c], acc);
    out[g * CC + c] = acc;
}

// ---------------------------------------------------------------------------
extern "C" void kernel_launch(void* const* d_in, const int* in_sizes, int n_in,
                              void* d_out, int out_size) {
    // Bind inputs by UNIQUE element counts (robust to metadata ordering)
    const float* x = nullptr;
    const float* W = nullptr;
    const float* b = nullptr;
    const float* lin_w = nullptr;
    const float* lin_b = nullptr;
    const int* edges = nullptr;
    const int* batch = nullptr;
    for (int i = 0; i < n_in; i++) {
        switch (in_sizes[i]) {
            case NN * DD:            x     = (const float*)d_in[i]; break;
            case LL * RR * DD * DD:  W     = (const float*)d_in[i]; break;
            case LL * RR * DD:       b     = (const float*)d_in[i]; break;
            case DD * CC:            lin_w = (const float*)d_in[i]; break;
            case CC:                 lin_b = (const float*)d_in[i]; break;
            case RR * 2 * EE:        edges = (const int*)d_in[i];   break;
            case NN:                 batch = (const int*)d_in[i];   break;
            default: break;
        }
    }
    float* out = (float*)d_out;                   // [G, C]

    const int TB = 256;

    // CSR build (recomputed every call; graph is layer-invariant)
    k_zero<<<(NTOT + TB - 1) / TB, TB>>>();
    k_deg<<<(RR * EE + TB - 1) / TB, TB>>>(edges);
    k_inv<<<(NTOT + TB - 1) / TB, TB>>>();
    k_scan1<<<NBLK, 1024>>>();
    k_scan2<<<1, 128>>>();
    k_scan3<<<(NTOT + TB - 1) / TB, TB>>>();
    k_fill<<<(RR * EE + TB - 1) / TB, TB>>>(edges);

    const int gemm_grid = (NN + 63) / 64;
    const int gath_blocks = (NN * 32 + TB - 1) / TB;
    const int pool_blocks = (NN * (DD / 4) + TB - 1) / TB;

    for (int l = 0; l < LL; l++) {
        k_gemm<<<dim3(gemm_grid, RR), 256>>>(x, l > 0 ? 1 : 0,
                                             W + (size_t)l * RR * DD * DD);
        k_gather<<<gath_blocks, TB>>>(b + (size_t)l * RR * DD,
                                      (l < LL - 1) ? 1 : 0);
    }

    k_pool<<<pool_blocks, TB>>>(batch);
    k_final<<<1, GG * CC>>>(lin_w, lin_b, out);
}

// round 14
// speedup vs baseline: 1.2432x; 1.2432x over previous
#include <cuda_runtime.h>
#include <cuda_bf16.h>
#include <cuda_fp16.h>

// Problem constants (fixed by dataset)
#define NN 50000
#define DD 128
#define EE 800000
#define RR 2
#define LL 2
#define GG 64
#define CC 8
#define NTOT (RR * NN)                 // 100000 CSR rows (relation-major)
#define NBLK ((NTOT + 1023) / 1024)    // 98 scan blocks

// Scratch (__device__ globals; never referenced from host code)
__device__ float   g_deg[NTOT];
__device__ float   g_inv[NTOT];
__device__ int     g_rowptr[NTOT + 1];
__device__ int     g_cursor[NTOT];
__device__ int     g_bsum[NBLK];
__device__ int     g_boff[NBLK];
__device__ int2    g_csr[RR * EE];       // (src, norm-as-int)
__device__ float   g_xw[RR * NN * DD];   // fp32 xw (self-loop path)
__device__ __half2 g_xwh[RR * NN * (DD / 2)]; // fp16 mirror for edge gathers
__device__ float   g_out[NN * DD];       // layer-2 output (pooled)
__device__ float   g_h[NN * DD];         // hidden after relu
__device__ float   g_sums[GG * DD];
__device__ float   g_cnt[GG];

__device__ __forceinline__ void red_add_v4(float* addr, float a, float b,
                                           float c, float d) {
    asm volatile("red.global.add.v4.f32 [%0], {%1, %2, %3, %4};"
                 :: "l"(addr), "f"(a), "f"(b), "f"(c), "f"(d) : "memory");
}

__device__ __forceinline__ unsigned f2tf32(float f) {
    unsigned u;
    asm("cvt.rna.tf32.f32 %0, %1;" : "=r"(u) : "f"(f));
    return u;
}

// ---------------------------------------------------------------------------
__global__ void k_zero() {
    int t = blockIdx.x * blockDim.x + threadIdx.x;
    if (t < NTOT) g_deg[t] = 0.f;
    if (t < GG * DD) g_sums[t] = 0.f;
    if (t < GG) g_cnt[t] = 0.f;
}

// degree count (dst side), per relation
__global__ void k_deg(const int* __restrict__ edges) {
    int t = blockIdx.x * blockDim.x + threadIdx.x;
    if (t >= RR * EE) return;
    int r = (t >= EE) ? 1 : 0;
    int e = t - r * EE;
    int dst = edges[r * 2 * EE + EE + e];
    atomicAdd(&g_deg[r * NN + dst], 1.f);
}

__global__ void k_inv() {
    int t = blockIdx.x * blockDim.x + threadIdx.x;
    if (t >= NTOT) return;
    g_inv[t] = rsqrtf(g_deg[t] + 1.f);
}

// ---------------------------------------------------------------------------
// multi-block scan, phase 1: per-block warp-shuffle scan (1024 threads/block)
__global__ void k_scan1() {
    __shared__ int wsum[32];
    int i = blockIdx.x * 1024 + threadIdx.x;
    int v = (i < NTOT) ? (int)g_deg[i] : 0;
    int lane = threadIdx.x & 31, w = threadIdx.x >> 5;
    int s = v;
#pragma unroll
    for (int o = 1; o < 32; o <<= 1) {
        int t = __shfl_up_sync(0xffffffffu, s, o);
        if (lane >= o) s += t;
    }
    if (lane == 31) wsum[w] = s;
    __syncthreads();
    if (w == 0) {
        int ws = wsum[lane];
#pragma unroll
        for (int o = 1; o < 32; o <<= 1) {
            int t = __shfl_up_sync(0xffffffffu, ws, o);
            if (lane >= o) ws += t;
        }
        wsum[lane] = ws;
    }
    __syncthreads();
    int excl = s - v + (w > 0 ? wsum[w - 1] : 0);
    if (i < NTOT) g_rowptr[i] = excl;
    if (threadIdx.x == 1023) g_bsum[blockIdx.x] = wsum[31];
}

// phase 2: single block (128 threads) scans the 98 block totals
__global__ void k_scan2() {
    __shared__ int wsum[4];
    int lane = threadIdx.x & 31, w = threadIdx.x >> 5;
    int v = (threadIdx.x < NBLK) ? g_bsum[threadIdx.x] : 0;
    int s = v;
#pragma unroll
    for (int o = 1; o < 32; o <<= 1) {
        int t = __shfl_up_sync(0xffffffffu, s, o);
        if (lane >= o) s += t;
    }
    if (lane == 31) wsum[w] = s;
    __syncthreads();
    int base = 0;
    for (int k = 0; k < w; k++) base += wsum[k];
    if (threadIdx.x < NBLK) g_boff[threadIdx.x] = base + s - v;
    if (threadIdx.x == 0) g_rowptr[NTOT] = RR * EE;   // total statically known
}

// phase 3: add block offsets
__global__ void k_scan3() {
    int i = blockIdx.x * blockDim.x + threadIdx.x;
    if (i >= NTOT) return;
    int val = g_rowptr[i] + g_boff[i >> 10];
    g_rowptr[i] = val;
    g_cursor[i] = val;
}

// scatter edge records into CSR buckets; norm precomputed (layer-invariant)
__global__ void k_fill(const int* __restrict__ edges) {
    int t = blockIdx.x * blockDim.x + threadIdx.x;
    if (t >= RR * EE) return;
    int r = (t >= EE) ? 1 : 0;
    int e = t - r * EE;
    int src = edges[r * 2 * EE + e];
    int dst = edges[r * 2 * EE + EE + e];
    int row = r * NN + dst;
    int pos = atomicAdd(&g_cursor[row], 1);
    float norm = g_inv[r * NN + src] * g_inv[row];
    g_csr[pos] = make_int2(src, __float_as_int(norm));
}

// ---------------------------------------------------------------------------
// Tensor-core GEMM (tf32 mma.sync, fp32 accum): XW[r] = A (N x 128) @ W (128 x 128)
// block = 256 thr (8 warps); block tile 128 rows; warp tile 16 rows x 128 cols.
// W staged in smem in two k-halves (stride 136 -> conflict-free B-frag LDS).
__global__ void __launch_bounds__(256, 2)
k_gemm(const float* __restrict__ x_in, int use_h, const float* __restrict__ Wl) {
    const float* __restrict__ A = use_h ? g_h : x_in;
    const int rel = blockIdx.y;
    const float* __restrict__ Wr = Wl + rel * DD * DD;
    float* __restrict__ out = g_xw + (size_t)rel * NN * DD;
    __half2* __restrict__ outh = g_xwh + (size_t)rel * NN * (DD / 2);

    __shared__ unsigned sW[64 * 136];      // tf32 bits, one k-half of W
    const int tid = threadIdx.x;
    const int lane = tid & 31;
    const int warp = tid >> 5;
    const int qr = lane >> 2;              // 0..7
    const int qc = lane & 3;               // 0..3

    const int row0 = blockIdx.x * 128 + warp * 16 + qr;
    const int row1 = row0 + 8;
    const bool v0 = row0 < NN;
    const bool v1 = row1 < NN;
    const float* __restrict__ a0p = A + (size_t)(v0 ? row0 : 0) * DD;
    const float* __restrict__ a1p = A + (size_t)(v1 ? row1 : 0) * DD;

    float acc[16][4];
#pragma unroll
    for (int n = 0; n < 16; n++)
#pragma unroll
        for (int i = 0; i < 4; i++) acc[n][i] = 0.f;

#pragma unroll
    for (int ph = 0; ph < 2; ph++) {
        __syncthreads();                   // protect prior phase's reads
        const float* __restrict__ wsrc = Wr + ph * 64 * DD;
#pragma unroll
        for (int i = 0; i < 32; i++) {
            int idx = i * 256 + tid;       // 0..8191
            int kk = idx >> 7, nn2 = idx & 127;
            sW[kk * 136 + nn2] = f2tf32(wsrc[kk * DD + nn2]);
        }
        __syncthreads();

#pragma unroll
        for (int kt = 0; kt < 8; kt++) {
            const int kg = ph * 64 + kt * 8;   // k in gmem
            const int ks = kt * 8;             // k in smem
            unsigned a0 = f2tf32(v0 ? a0p[kg + qc] : 0.f);
            unsigned a1 = f2tf32(v1 ? a1p[kg + qc] : 0.f);
            unsigned a2 = f2tf32(v0 ? a0p[kg + qc + 4] : 0.f);
            unsigned a3 = f2tf32(v1 ? a1p[kg + qc + 4] : 0.f);
#pragma unroll
            for (int nt = 0; nt < 16; nt++) {
                unsigned b0 = sW[(ks + qc) * 136 + nt * 8 + qr];
                unsigned b1 = sW[(ks + qc + 4) * 136 + nt * 8 + qr];
                asm("mma.sync.aligned.m16n8k8.row.col.f32.tf32.tf32.f32 "
                    "{%0,%1,%2,%3}, {%4,%5,%6,%7}, {%8,%9}, {%0,%1,%2,%3};"
                    : "+f"(acc[nt][0]), "+f"(acc[nt][1]),
                      "+f"(acc[nt][2]), "+f"(acc[nt][3])
                    : "r"(a0), "r"(a1), "r"(a2), "r"(a3), "r"(b0), "r"(b1));
            }
        }
    }

    // epilogue: c0,c1 -> (row0, nt*8 + 2*qc); c2,c3 -> (row1, same cols)
#pragma unroll
    for (int nt = 0; nt < 16; nt++) {
        int col = nt * 8 + qc * 2;
        if (v0) {
            *(float2*)&out[(size_t)row0 * DD + col] =
                make_float2(acc[nt][0], acc[nt][1]);
            outh[(size_t)row0 * (DD / 2) + (col >> 1)] =
                __floats2half2_rn(acc[nt][0], acc[nt][1]);
        }
        if (v1) {
            *(float2*)&out[(size_t)row1 * DD + col] =
                make_float2(acc[nt][2], acc[nt][3]);
            outh[(size_t)row1 * (DD / 2) + (col >> 1)] =
                __floats2half2_rn(acc[nt][2], acc[nt][3]);
        }
    }
}

// ---------------------------------------------------------------------------
// CSR gather: warp per node, lane owns 4 cols. Self-loop + biases in fp32;
// edge messages read the fp16 mirror, accumulate fp32.
__global__ void k_gather(const float* __restrict__ bvec, int store_relu) {
    int gw = (blockIdx.x * blockDim.x + threadIdx.x) >> 5;
    if (gw >= NN) return;
    const int lane = threadIdx.x & 31;
    const int n = gw;
    const int c = lane * 4;

    float4 b0 = *(const float4*)&bvec[c];
    float4 b1 = *(const float4*)&bvec[DD + c];
    float i0 = g_inv[n];
    float i1 = g_inv[NN + n];
    float4 x0 = *(const float4*)&g_xw[(size_t)n * DD + c];
    float4 x1 = *(const float4*)&g_xw[(size_t)(NN + n) * DD + c];

    float4 acc;
    acc.x = b0.x + b1.x + x0.x * i0 * i0 + x1.x * i1 * i1;
    acc.y = b0.y + b1.y + x0.y * i0 * i0 + x1.y * i1 * i1;
    acc.z = b0.z + b1.z + x0.z * i0 * i0 + x1.z * i1 * i1;
    acc.w = b0.w + b1.w + x0.w * i0 * i0 + x1.w * i1 * i1;

#pragma unroll
    for (int r = 0; r < RR; r++) {
        const __half2* __restrict__ xwh = g_xwh + (size_t)r * NN * (DD / 2);
        int row = r * NN + n;
        int s0 = g_rowptr[row];
        int s1 = g_rowptr[row + 1];
#pragma unroll 2
        for (int j = s0; j < s1; j++) {
            int2 ed = __ldg(&g_csr[j]);
            float norm = __int_as_float(ed.y);
            union { uint2 u; __half2 h[2]; } pk;
            pk.u = __ldg((const uint2*)&xwh[(size_t)ed.x * (DD / 2) + lane * 2]);
            float2 lo = __half22float2(pk.h[0]);
            float2 hi = __half22float2(pk.h[1]);
            acc.x = fmaf(lo.x, norm, acc.x);
            acc.y = fmaf(lo.y, norm, acc.y);
            acc.z = fmaf(hi.x, norm, acc.z);
            acc.w = fmaf(hi.y, norm, acc.w);
        }
    }

    float* dst = store_relu ? g_h : g_out;
    if (store_relu) {
        acc.x = fmaxf(acc.x, 0.f); acc.y = fmaxf(acc.y, 0.f);
        acc.z = fmaxf(acc.z, 0.f); acc.w = fmaxf(acc.w, 0.f);
    }
    *(float4*)&dst[(size_t)n * DD + c] = acc;
}

// ---------------------------------------------------------------------------
// global mean pool: v4 reductions, 4 floats per thread
__global__ void k_pool(const int* __restrict__ batch) {
    int t = blockIdx.x * blockDim.x + threadIdx.x;
    if (t >= NN * (DD / 4)) return;
    int n = t >> 5;
    int c4 = (t & 31) * 4;
    int g = batch[n];
    float4 v = *(const float4*)&g_out[(size_t)n * DD + c4];
    red_add_v4(&g_sums[g * DD + c4], v.x, v.y, v.z, v.w);
    if (c4 == 0) atomicAdd(&g_cnt[g], 1.f);
}

__global__ void k_final(const float* __restrict__ lw, const float* __restrict__ lb,
                        float* __restrict__ out) {
    int t = threadIdx.x;          // 512 = G*C
    int g = t >> 3, c = t & 7;
    float inv = 1.f / fmaxf(g_cnt[g], 1.f);
    float acc = lb[c];
#pragma unroll 8
    for (int d = 0; d < DD; d++)
        acc = fmaf(g_sums[g * DD + d] * inv, lw[d * CC + c], acc);
    out[g * CC + c] = acc;
}

// ---------------------------------------------------------------------------
extern "C" void kernel_launch(void* const* d_in, const int* in_sizes, int n_in,
                              void* d_out, int out_size) {
    // Bind inputs by UNIQUE element counts (robust to metadata ordering)
    const float* x = nullptr;
    const float* W = nullptr;
    const float* b = nullptr;
    const float* lin_w = nullptr;
    const float* lin_b = nullptr;
    const int* edges = nullptr;
    const int* batch = nullptr;
    for (int i = 0; i < n_in; i++) {
        switch (in_sizes[i]) {
            case NN * DD:            x     = (const float*)d_in[i]; break;
            case LL * RR * DD * DD:  W     = (const float*)d_in[i]; break;
            case LL * RR * DD:       b     = (const float*)d_in[i]; break;
            case DD * CC:            lin_w = (const float*)d_in[i]; break;
            case CC:                 lin_b = (const float*)d_in[i]; break;
            case RR * 2 * EE:        edges = (const int*)d_in[i];   break;
            case NN:                 batch = (const int*)d_in[i];   break;
            default: break;
        }
    }
    float* out = (float*)d_out;                   // [G, C]

    const int TB = 256;

    // CSR build (recomputed every call; graph is layer-invariant)
    k_zero<<<(NTOT + TB - 1) / TB, TB>>>();
    k_deg<<<(RR * EE + TB - 1) / TB, TB>>>(edges);
    k_inv<<<(NTOT + TB - 1) / TB, TB>>>();
    k_scan1<<<NBLK, 1024>>>();
    k_scan2<<<1, 128>>>();
    k_scan3<<<(NTOT + TB - 1) / TB, TB>>>();
    k_fill<<<(RR * EE + TB - 1) / TB, TB>>>(edges);

    const int gemm_grid = (NN + 127) / 128;
    const int gath_blocks = (NN * 32 + TB - 1) / TB;
    const int pool_blocks = (NN * (DD / 4) + TB - 1) / TB;

    for (int l = 0; l < LL; l++) {
        k_gemm<<<dim3(gemm_grid, RR), 256>>>(x, l > 0 ? 1 : 0,
                                             W + (size_t)l * RR * DD * DD);
        k_gather<<<gath_blocks, TB>>>(b + (size_t)l * RR * DD,
                                      (l < LL - 1) ? 1 : 0);
    }

    k_pool<<<pool_blocks, TB>>>(batch);
    k_final<<<1, GG * CC>>>(lin_w, lin_b, out);
}

// round 16
// speedup vs baseline: 1.4180x; 1.1406x over previous
#include <cuda_runtime.h>
#include <cuda_bf16.h>
#include <cuda_fp16.h>

// Problem constants (fixed by dataset)
#define NN 50000
#define DD 128
#define EE 800000
#define RR 2
#define LL 2
#define GG 64
#define CC 8
#define NTOT (RR * NN)                 // 100000 CSR rows (relation-major)
#define NBLK ((NTOT + 1023) / 1024)    // 98 scan blocks

// Scratch (__device__ globals; never referenced from host code)
__device__ float   g_deg[NTOT];
__device__ float   g_inv[NTOT];
__device__ int     g_rowptr[NTOT + 1];
__device__ int     g_cursor[NTOT];
__device__ int     g_bsum[NBLK];
__device__ int     g_boff[NBLK];
__device__ int2    g_csr[RR * EE];            // (src, norm-as-int)
__device__ __half2 g_xwh[RR * NN * (DD / 2)]; // fp16 XW (sole GEMM output)
__device__ float   g_out[NN * DD];            // layer-2 output (pooled)
__device__ float   g_h[NN * DD];              // hidden after relu
__device__ float   g_sums[GG * DD];
__device__ float   g_cnt[GG];

__device__ __forceinline__ void red_add_v4(float* addr, float a, float b,
                                           float c, float d) {
    asm volatile("red.global.add.v4.f32 [%0], {%1, %2, %3, %4};"
                 :: "l"(addr), "f"(a), "f"(b), "f"(c), "f"(d) : "memory");
}

__device__ __forceinline__ unsigned f2tf32(float f) {
    unsigned u;
    asm("cvt.rna.tf32.f32 %0, %1;" : "=r"(u) : "f"(f));
    return u;
}

// ---------------------------------------------------------------------------
__global__ void k_zero() {
    int t = blockIdx.x * blockDim.x + threadIdx.x;
    if (t < NTOT) g_deg[t] = 0.f;
    if (t < GG * DD) g_sums[t] = 0.f;
    if (t < GG) g_cnt[t] = 0.f;
}

// degree count (dst side), per relation
__global__ void k_deg(const int* __restrict__ edges) {
    int t = blockIdx.x * blockDim.x + threadIdx.x;
    if (t >= RR * EE) return;
    int r = (t >= EE) ? 1 : 0;
    int e = t - r * EE;
    int dst = edges[r * 2 * EE + EE + e];
    atomicAdd(&g_deg[r * NN + dst], 1.f);
}

// ---------------------------------------------------------------------------
// scan phase 1 (fused with inv_sqrt_deg): per-block warp-shuffle scan
__global__ void k_scan1() {
    __shared__ int wsum[32];
    int i = blockIdx.x * 1024 + threadIdx.x;
    float dg = (i < NTOT) ? g_deg[i] : 0.f;
    if (i < NTOT) g_inv[i] = rsqrtf(dg + 1.f);
    int v = (int)dg;
    int lane = threadIdx.x & 31, w = threadIdx.x >> 5;
    int s = v;
#pragma unroll
    for (int o = 1; o < 32; o <<= 1) {
        int t = __shfl_up_sync(0xffffffffu, s, o);
        if (lane >= o) s += t;
    }
    if (lane == 31) wsum[w] = s;
    __syncthreads();
    if (w == 0) {
        int ws = wsum[lane];
#pragma unroll
        for (int o = 1; o < 32; o <<= 1) {
            int t = __shfl_up_sync(0xffffffffu, ws, o);
            if (lane >= o) ws += t;
        }
        wsum[lane] = ws;
    }
    __syncthreads();
    int excl = s - v + (w > 0 ? wsum[w - 1] : 0);
    if (i < NTOT) g_rowptr[i] = excl;
    if (threadIdx.x == 1023) g_bsum[blockIdx.x] = wsum[31];
}

// phase 2: single block scans the 98 block totals
__global__ void k_scan2() {
    __shared__ int wsum[4];
    int lane = threadIdx.x & 31, w = threadIdx.x >> 5;
    int v = (threadIdx.x < NBLK) ? g_bsum[threadIdx.x] : 0;
    int s = v;
#pragma unroll
    for (int o = 1; o < 32; o <<= 1) {
        int t = __shfl_up_sync(0xffffffffu, s, o);
        if (lane >= o) s += t;
    }
    if (lane == 31) wsum[w] = s;
    __syncthreads();
    int base = 0;
    for (int k = 0; k < w; k++) base += wsum[k];
    if (threadIdx.x < NBLK) g_boff[threadIdx.x] = base + s - v;
    if (threadIdx.x == 0) g_rowptr[NTOT] = RR * EE;
}

// phase 3: add block offsets
__global__ void k_scan3() {
    int i = blockIdx.x * blockDim.x + threadIdx.x;
    if (i >= NTOT) return;
    int val = g_rowptr[i] + g_boff[i >> 10];
    g_rowptr[i] = val;
    g_cursor[i] = val;
}

// scatter edge records into CSR buckets; norm precomputed (layer-invariant)
__global__ void k_fill(const int* __restrict__ edges) {
    int t = blockIdx.x * blockDim.x + threadIdx.x;
    if (t >= RR * EE) return;
    int r = (t >= EE) ? 1 : 0;
    int e = t - r * EE;
    int src = edges[r * 2 * EE + e];
    int dst = edges[r * 2 * EE + EE + e];
    int row = r * NN + dst;
    int pos = atomicAdd(&g_cursor[row], 1);
    float norm = g_inv[r * NN + src] * g_inv[row];
    g_csr[pos] = make_int2(src, __float_as_int(norm));
}

// ---------------------------------------------------------------------------
// Tensor-core GEMM (tf32 mma.sync, fp32 accum), fp16-only output.
__global__ void __launch_bounds__(256, 2)
k_gemm(const float* __restrict__ x_in, int use_h, const float* __restrict__ Wl) {
    const float* __restrict__ A = use_h ? g_h : x_in;
    const int rel = blockIdx.y;
    const float* __restrict__ Wr = Wl + rel * DD * DD;
    __half2* __restrict__ outh = g_xwh + (size_t)rel * NN * (DD / 2);

    __shared__ unsigned sW[64 * 136];      // tf32 bits, one k-half of W
    const int tid = threadIdx.x;
    const int lane = tid & 31;
    const int warp = tid >> 5;
    const int qr = lane >> 2;              // 0..7
    const int qc = lane & 3;               // 0..3

    const int row0 = blockIdx.x * 128 + warp * 16 + qr;
    const int row1 = row0 + 8;
    const bool v0 = row0 < NN;
    const bool v1 = row1 < NN;
    const float* __restrict__ a0p = A + (size_t)(v0 ? row0 : 0) * DD;
    const float* __restrict__ a1p = A + (size_t)(v1 ? row1 : 0) * DD;

    float acc[16][4];
#pragma unroll
    for (int n = 0; n < 16; n++)
#pragma unroll
        for (int i = 0; i < 4; i++) acc[n][i] = 0.f;

#pragma unroll
    for (int ph = 0; ph < 2; ph++) {
        __syncthreads();
        const float* __restrict__ wsrc = Wr + ph * 64 * DD;
#pragma unroll
        for (int i = 0; i < 32; i++) {
            int idx = i * 256 + tid;
            int kk = idx >> 7, nn2 = idx & 127;
            sW[kk * 136 + nn2] = f2tf32(wsrc[kk * DD + nn2]);
        }
        __syncthreads();

#pragma unroll
        for (int kt = 0; kt < 8; kt++) {
            const int kg = ph * 64 + kt * 8;
            const int ks = kt * 8;
            unsigned a0 = f2tf32(v0 ? a0p[kg + qc] : 0.f);
            unsigned a1 = f2tf32(v1 ? a1p[kg + qc] : 0.f);
            unsigned a2 = f2tf32(v0 ? a0p[kg + qc + 4] : 0.f);
            unsigned a3 = f2tf32(v1 ? a1p[kg + qc + 4] : 0.f);
#pragma unroll
            for (int nt = 0; nt < 16; nt++) {
                unsigned b0 = sW[(ks + qc) * 136 + nt * 8 + qr];
                unsigned b1 = sW[(ks + qc + 4) * 136 + nt * 8 + qr];
                asm("mma.sync.aligned.m16n8k8.row.col.f32.tf32.tf32.f32 "
                    "{%0,%1,%2,%3}, {%4,%5,%6,%7}, {%8,%9}, {%0,%1,%2,%3};"
                    : "+f"(acc[nt][0]), "+f"(acc[nt][1]),
                      "+f"(acc[nt][2]), "+f"(acc[nt][3])
                    : "r"(a0), "r"(a1), "r"(a2), "r"(a3), "r"(b0), "r"(b1));
            }
        }
    }

#pragma unroll
    for (int nt = 0; nt < 16; nt++) {
        int col = nt * 8 + qc * 2;
        if (v0)
            outh[(size_t)row0 * (DD / 2) + (col >> 1)] =
                __floats2half2_rn(acc[nt][0], acc[nt][1]);
        if (v1)
            outh[(size_t)row1 * (DD / 2) + (col >> 1)] =
                __floats2half2_rn(acc[nt][2], acc[nt][3]);
    }
}

// ---------------------------------------------------------------------------
// CSR gather: warp per node, lane owns 4 cols. Edge loop unrolled x4 with
// batched loads (MLP=4) to hide L2 latency. fp32 accumulation throughout.
__global__ void k_gather(const float* __restrict__ bvec, int store_relu) {
    int gw = (blockIdx.x * blockDim.x + threadIdx.x) >> 5;
    if (gw >= NN) return;
    const int lane = threadIdx.x & 31;
    const int n = gw;
    const int c = lane * 4;

    float4 b0 = *(const float4*)&bvec[c];
    float4 b1 = *(const float4*)&bvec[DD + c];
    float i0 = g_inv[n];
    float i1 = g_inv[NN + n];

    // self-loop terms from the fp16 XW
    union { uint2 u; __half2 h[2]; } s0u, s1u;
    s0u.u = __ldg((const uint2*)&g_xwh[(size_t)n * (DD / 2) + lane * 2]);
    s1u.u = __ldg((const uint2*)&g_xwh[(size_t)(NN + n) * (DD / 2) + lane * 2]);
    float2 s0lo = __half22float2(s0u.h[0]), s0hi = __half22float2(s0u.h[1]);
    float2 s1lo = __half22float2(s1u.h[0]), s1hi = __half22float2(s1u.h[1]);

    float4 acc;
    acc.x = b0.x + b1.x + s0lo.x * i0 * i0 + s1lo.x * i1 * i1;
    acc.y = b0.y + b1.y + s0lo.y * i0 * i0 + s1lo.y * i1 * i1;
    acc.z = b0.z + b1.z + s0hi.x * i0 * i0 + s1hi.x * i1 * i1;
    acc.w = b0.w + b1.w + s0hi.y * i0 * i0 + s1hi.y * i1 * i1;

#pragma unroll
    for (int r = 0; r < RR; r++) {
        const __half2* __restrict__ xwh = g_xwh + (size_t)r * NN * (DD / 2);
        int row = r * NN + n;
        int j = g_rowptr[row];
        int s1 = g_rowptr[row + 1];

        for (; j + 4 <= s1; j += 4) {
            int2 e0 = __ldg(&g_csr[j]);
            int2 e1 = __ldg(&g_csr[j + 1]);
            int2 e2 = __ldg(&g_csr[j + 2]);
            int2 e3 = __ldg(&g_csr[j + 3]);
            union { uint2 u; __half2 h[2]; } p0, p1, p2, p3;
            p0.u = __ldg((const uint2*)&xwh[(size_t)e0.x * (DD / 2) + lane * 2]);
            p1.u = __ldg((const uint2*)&xwh[(size_t)e1.x * (DD / 2) + lane * 2]);
            p2.u = __ldg((const uint2*)&xwh[(size_t)e2.x * (DD / 2) + lane * 2]);
            p3.u = __ldg((const uint2*)&xwh[(size_t)e3.x * (DD / 2) + lane * 2]);
            float n0 = __int_as_float(e0.y), n1 = __int_as_float(e1.y);
            float n2 = __int_as_float(e2.y), n3 = __int_as_float(e3.y);
            float2 lo, hi;
            lo = __half22float2(p0.h[0]); hi = __half22float2(p0.h[1]);
            acc.x = fmaf(lo.x, n0, acc.x); acc.y = fmaf(lo.y, n0, acc.y);
            acc.z = fmaf(hi.x, n0, acc.z); acc.w = fmaf(hi.y, n0, acc.w);
            lo = __half22float2(p1.h[0]); hi = __half22float2(p1.h[1]);
            acc.x = fmaf(lo.x, n1, acc.x); acc.y = fmaf(lo.y, n1, acc.y);
            acc.z = fmaf(hi.x, n1, acc.z); acc.w = fmaf(hi.y, n1, acc.w);
            lo = __half22float2(p2.h[0]); hi = __half22float2(p2.h[1]);
            acc.x = fmaf(lo.x, n2, acc.x); acc.y = fmaf(lo.y, n2, acc.y);
            acc.z = fmaf(hi.x, n2, acc.z); acc.w = fmaf(hi.y, n2, acc.w);
            lo = __half22float2(p3.h[0]); hi = __half22float2(p3.h[1]);
            acc.x = fmaf(lo.x, n3, acc.x); acc.y = fmaf(lo.y, n3, acc.y);
            acc.z = fmaf(hi.x, n3, acc.z); acc.w = fmaf(hi.y, n3, acc.w);
        }
        for (; j < s1; j++) {
            int2 ed = __ldg(&g_csr[j]);
            float norm = __int_as_float(ed.y);
            union { uint2 u; __half2 h[2]; } pk;
            pk.u = __ldg((const uint2*)&xwh[(size_t)ed.x * (DD / 2) + lane * 2]);
            float2 lo = __half22float2(pk.h[0]);
            float2 hi = __half22float2(pk.h[1]);
            acc.x = fmaf(lo.x, norm, acc.x);
            acc.y = fmaf(lo.y, norm, acc.y);
            acc.z = fmaf(hi.x, norm, acc.z);
            acc.w = fmaf(hi.y, norm, acc.w);
        }
    }

    float* dst = store_relu ? g_h : g_out;
    if (store_relu) {
        acc.x = fmaxf(acc.x, 0.f); acc.y = fmaxf(acc.y, 0.f);
        acc.z = fmaxf(acc.z, 0.f); acc.w = fmaxf(acc.w, 0.f);
    }
    *(float4*)&dst[(size_t)n * DD + c] = acc;
}

// ---------------------------------------------------------------------------
// global mean pool: v4 reductions, 4 floats per thread
__global__ void k_pool(const int* __restrict__ batch) {
    int t = blockIdx.x * blockDim.x + threadIdx.x;
    if (t >= NN * (DD / 4)) return;
    int n = t >> 5;
    int c4 = (t & 31) * 4;
    int g = batch[n];
    float4 v = *(const float4*)&g_out[(size_t)n * DD + c4];
    red_add_v4(&g_sums[g * DD + c4], v.x, v.y, v.z, v.w);
    if (c4 == 0) atomicAdd(&g_cnt[g], 1.f);
}

__global__ void k_final(const float* __restrict__ lw, const float* __restrict__ lb,
                        float* __restrict__ out) {
    int t = threadIdx.x;          // 512 = G*C
    int g = t >> 3, c = t & 7;
    float inv = 1.f / fmaxf(g_cnt[g], 1.f);
    float acc = lb[c];
#pragma unroll 8
    for (int d = 0; d < DD; d++)
        acc = fmaf(g_sums[g * DD + d] * inv, lw[d * CC + c], acc);
    out[g * CC + c] = acc;
}

// ---------------------------------------------------------------------------
extern "C" void kernel_launch(void* const* d_in, const int* in_sizes, int n_in,
                              void* d_out, int out_size) {
    // Bind inputs by UNIQUE element counts (robust to metadata ordering)
    const float* x = nullptr;
    const float* W = nullptr;
    const float* b = nullptr;
    const float* lin_w = nullptr;
    const float* lin_b = nullptr;
    const int* edges = nullptr;
    const int* batch = nullptr;
    for (int i = 0; i < n_in; i++) {
        switch (in_sizes[i]) {
            case NN * DD:            x     = (const float*)d_in[i]; break;
            case LL * RR * DD * DD:  W     = (const float*)d_in[i]; break;
            case LL * RR * DD:       b     = (const float*)d_in[i]; break;
            case DD * CC:            lin_w = (const float*)d_in[i]; break;
            case CC:                 lin_b = (const float*)d_in[i]; break;
            case RR * 2 * EE:        edges = (const int*)d_in[i];   break;
            case NN:                 batch = (const int*)d_in[i];   break;
            default: break;
        }
    }
    float* out = (float*)d_out;                   // [G, C]

    const int TB = 256;

    // CSR build (recomputed every call; graph is layer-invariant)
    k_zero<<<(NTOT + TB - 1) / TB, TB>>>();
    k_deg<<<(RR * EE + TB - 1) / TB, TB>>>(edges);
    k_scan1<<<NBLK, 1024>>>();
    k_scan2<<<1, 128>>>();
    k_scan3<<<(NTOT + TB - 1) / TB, TB>>>();
    k_fill<<<(RR * EE + TB - 1) / TB, TB>>>(edges);

    const int gemm_grid = (NN + 127) / 128;
    const int gath_blocks = (NN * 32 + TB - 1) / TB;
    const int pool_blocks = (NN * (DD / 4) + TB - 1) / TB;

    for (int l = 0; l < LL; l++) {
        k_gemm<<<dim3(gemm_grid, RR), 256>>>(x, l > 0 ? 1 : 0,
                                             W + (size_t)l * RR * DD * DD);
        k_gather<<<gath_blocks, TB>>>(b + (size_t)l * RR * DD,
                                      (l < LL - 1) ? 1 : 0);
    }

    k_pool<<<pool_blocks, TB>>>(batch);
    k_final<<<1, GG * CC>>>(lin_w, lin_b, out);
}